// round 15
// baseline (speedup 1.0000x reference)
#include <cuda_runtime.h>
#include <cuda_fp16.h>
#include <math.h>

#define BATCH  32768
#define NWARPS 8
#define THREADS (NWARPS * 32)
#define NBLOCKS (BATCH / (NWARPS * 2))   // 2048: 2 matrices per warp, 8 warps/block
#define NSWEEP 3
#define H2STR 28                         // row stride in half2 units (112B, 16B-aligned)

__device__ double g_pd[NBLOCKS][4];   // sum_eig, sum_s, sum_fro, sum_absO
__device__ float  g_pmx[NBLOCKS];
__device__ float  g_pmn[NBLOCKS];

static __device__ __forceinline__ unsigned h2u(__half2 h) { return *reinterpret_cast<unsigned*>(&h); }
static __device__ __forceinline__ __half2  u2h(unsigned u) { return *reinterpret_cast<__half2*>(&u); }

__global__ __launch_bounds__(THREADS)
void cond_main_kernel(const float* __restrict__ inp, const float* __restrict__ outp) {
    __shared__ __align__(16) __half2 Osh[NWARPS][25 * H2STR + 8];
    __shared__ double redd[NWARPS][4];
    __shared__ float  redmx[NWARPS];
    __shared__ float  redmn[NWARPS];

    const int w    = threadIdx.x >> 5;
    const int lane = threadIdx.x & 31;
    const int wg   = blockIdx.x * NWARPS + w;
    const int b0   = 2 * wg;               // this warp handles matrices b0, b0+1
    __half2* Os2 = Osh[w];

    const bool act25 = (lane < 25);
    const unsigned FULL = 0xffffffffu;

    const __half2 ONE2   = __float2half2_rn(1.0f);
    const __half2 ZERO2  = __float2half2_rn(0.0f);
    const __half2 EPSDEN = __float2half2_rn(1e-4f);
    const __half2 EIGHTH = __float2half2_rn(0.125f);
    const __half2 BMIN   = __float2half2_rn(0.3398f);   // alpha-max-beta-min hypot coeff

    float absO = 0.f;
    float froA = 0.f, froB = 0.f;
    float alA = 0.f, alB = 0.f;    // fp32 per-column ||col||^2 (trace source)
    __half2 v2[25];                // lo = matrix A column elem, hi = matrix B (x 1/8)

    // ---- prologue: load both O matrices packed, packed GEMM C = O@I ----
    {
        const float* OA = outp + (size_t)b0 * 625;
        const float* OB = OA + 625;
        const float* IA = inp + (size_t)b0 * 625;
        const float* IB = IA + 625;

        for (int idx = lane; idx < 625; idx += 32) {
            float a = OA[idx];
            float bv = OB[idx];
            absO += fabsf(a) + fabsf(bv);
            int i = idx / 25, j = idx - i * 25;
            Os2[i * H2STR + j] = __floats2half2_rn(a, bv);
        }
        __half2 Icol2[25];
        #pragma unroll
        for (int k = 0; k < 25; k++) {
            float a = act25 ? IA[k * 25 + lane] : 0.f;
            float bv = act25 ? IB[k * 25 + lane] : 0.f;
            Icol2[k] = __floats2half2_rn(a, bv);
        }
        __syncwarp();

        #pragma unroll
        for (int i = 0; i < 25; i++) {
            const uint4* row4 = reinterpret_cast<const uint4*>(Os2 + i * H2STR);
            __half2 acc = ZERO2;
            #pragma unroll
            for (int q = 0; q < 6; q++) {
                uint4 p = row4[q];
                acc = __hfma2(u2h(p.x), Icol2[4 * q + 0], acc);
                acc = __hfma2(u2h(p.y), Icol2[4 * q + 1], acc);
                acc = __hfma2(u2h(p.z), Icol2[4 * q + 2], acc);
                acc = __hfma2(u2h(p.w), Icol2[4 * q + 3], acc);
            }
            acc = __hfma2(Os2[i * H2STR + 24], Icol2[24], acc);
            float2 cf = __half22float2(acc);
            alA = fmaf(cf.x, cf.x, alA);
            alB = fmaf(cf.y, cf.y, alB);
            float eye = (i == lane) ? 1.f : 0.f;
            float dA = cf.x - eye, dB = cf.y - eye;
            if (act25) { froA = fmaf(dA, dA, froA); froB = fmaf(dB, dB, froB); }
            v2[i] = __hmul2(acc, EIGHTH);
        }
    }

    // alpha in scaled units (1/64), packed (A,B)
    __half2 a2 = __floats2half2_rn(alA * (1.f / 64.f), alB * (1.f / 64.f));
    __half2 f2  = ONE2;   // deferred column scale (product of cosines)
    __half2 rf2 = ONE2;   // 1/f, tracked incrementally

    int partner0 = (lane == 0) ? 0 : (25 - lane);
    if (lane >= 25) partner0 = 0;
    int partner = partner0;

    // One Jacobi round (tangent form, homogeneous-t, packed 2 matrices).
    auto round_body = [&]() {
        const bool active = act25 && (partner != lane);

        __half2 o2[25];
        __half2 d0 = ZERO2, d1 = ZERO2;
        #pragma unroll
        for (int i = 0; i < 12; i++) {
            o2[i] = u2h(__shfl_sync(FULL, h2u(v2[i]), partner));
            d0 = __hfma2(v2[i], o2[i], d0);
        }
        #pragma unroll
        for (int i = 12; i < 25; i++) {
            o2[i] = u2h(__shfl_sync(FULL, h2u(v2[i]), partner));
            d1 = __hfma2(v2[i], o2[i], d1);
        }
        __half2 vdot = __hadd2(d0, d1);
        __half2 a2o = u2h(__shfl_sync(FULL, h2u(a2), partner));
        __half2 f2o = u2h(__shfl_sync(FULL, h2u(f2), partner));

        __half2 g2  = __hmul2(__hmul2(f2, f2o), vdot);   // true <col,col_o>
        __half2 num = __hsub2(a2o, a2);
        __half2 tg  = __hadd2(g2, g2);                   // 2*gamma
        // t = 2g*sign(num) / (|num| + rad), rad ~ hypot(num, 2g) via amax+bmin
        __half2 ax = __habs2(num);
        __half2 ag = __habs2(tg);
        __half2 mx = __hmax2(ax, ag);
        __half2 mn = __hmin2(ax, ag);
        __half2 rad = __hfma2(mn, BMIN, mx);
        __half2 denom = __hmax2(__hadd2(ax, rad), EPSDEN);
        __half2 tnum = u2h(h2u(tg) ^ (h2u(num) & 0x80008000u));
        __half2 t2 = __hmul2(tnum, h2rcp(denom));
        if (!active) t2 = ZERO2;

        __half2 nt2 = __hneg2(t2);
        __half2 q2  = __hfma2(t2, t2, ONE2);   // 1 + t^2
        __half2 rq2 = h2rsqrt(q2);             // = c
        __half2 coef = __hmul2(nt2, __hmul2(f2o, rf2));
        #pragma unroll
        for (int i = 0; i < 25; i++)
            v2[i] = __hfma2(coef, o2[i], v2[i]);

        a2 = __hfma2(nt2, g2, a2);               // alpha' = alpha - t*gamma
        f2  = __hmul2(f2, rq2);                  // f *= c
        rf2 = __hmul2(rf2, __hmul2(q2, rq2));    // rf *= 1/c

        partner += 2;
        if (partner >= 25) partner -= 25;
    };

    // ---- packed one-sided Jacobi: 25 rounds/sweep = 6 groups of 4 + 1 ----
    for (int sweep = 0; sweep < NSWEEP; sweep++) {
        partner = partner0;
        #pragma unroll 1
        for (int g = 0; g < 6; g++) {
            round_body(); round_body(); round_body(); round_body();
            // renorm once per 4 rounds: f >= 0.0625 guaranteed between checks
            if (__low2float(f2) < 0.25f || __high2float(f2) < 0.25f) {
                #pragma unroll
                for (int i = 0; i < 25; i++) v2[i] = __hmul2(v2[i], f2);
                f2 = ONE2;
                rf2 = ONE2;
            }
        }
        round_body();
        // sweep end: fold scale; (half) alpha refresh kills drift
        #pragma unroll
        for (int i = 0; i < 25; i++) v2[i] = __hmul2(v2[i], f2);
        f2 = ONE2;
        rf2 = ONE2;
        if (sweep != NSWEEP - 1) {
            __half2 acc0 = ZERO2, acc1 = ZERO2;
            #pragma unroll
            for (int i = 0; i < 12; i++) acc0 = __hfma2(v2[i], v2[i], acc0);
            #pragma unroll
            for (int i = 12; i < 25; i++) acc1 = __hfma2(v2[i], v2[i], acc1);
            a2 = __hadd2(acc0, acc1);
        }
    }

    // ---- final norms in fp32 (scale back by 64) ----
    float aA = 0.f, aB = 0.f;
    #pragma unroll
    for (int i = 0; i < 25; i++) {
        float2 cf = __half22float2(v2[i]);
        aA = fmaf(cf.x, cf.x, aA);
        aB = fmaf(cf.y, cf.y, aB);
    }
    aA *= 64.f; aB *= 64.f;

    float acA = fmaxf(aA, 1e-12f), acB = fmaxf(aB, 1e-12f);
    // Sum S^2 from fp32 prologue alphas (trace invariance) — not from fp16 Jacobi.
    float suma = act25 ? (alA + alB) : 0.f;
    float sums = act25 ? (sqrtf(aA) + sqrtf(aB)) : 0.f;
    float mxa  = act25 ? fmaxf(acA, acB) : 0.f;
    float mna  = act25 ? fminf(acA, acB) : 3.0e38f;

    #pragma unroll
    for (int off = 16; off > 0; off >>= 1) {
        suma += __shfl_xor_sync(FULL, suma, off);
        sums += __shfl_xor_sync(FULL, sums, off);
        froA += __shfl_xor_sync(FULL, froA, off);
        froB += __shfl_xor_sync(FULL, froB, off);
        absO += __shfl_xor_sync(FULL, absO, off);
        mxa = fmaxf(mxa, __shfl_xor_sync(FULL, mxa, off));
        mna = fminf(mna, __shfl_xor_sync(FULL, mna, off));
    }
    if (lane == 0) {
        redd[w][0] = (double)suma;
        redd[w][1] = (double)sums;
        redd[w][2] = (double)(sqrtf(froA) + sqrtf(froB));
        redd[w][3] = (double)absO;
        redmx[w] = mxa;
        redmn[w] = mna;
    }
    __syncthreads();

    if (threadIdx.x == 0) {
        double s0 = 0.0, s1 = 0.0, s2 = 0.0, s3 = 0.0;
        float mx = 0.f, mn = 3.0e38f;
        #pragma unroll
        for (int i = 0; i < NWARPS; i++) {
            s0 += redd[i][0]; s1 += redd[i][1]; s2 += redd[i][2]; s3 += redd[i][3];
            mx = fmaxf(mx, redmx[i]);
            mn = fminf(mn, redmn[i]);
        }
        g_pd[blockIdx.x][0] = s0;
        g_pd[blockIdx.x][1] = s1;
        g_pd[blockIdx.x][2] = s2;
        g_pd[blockIdx.x][3] = s3;
        g_pmx[blockIdx.x] = mx;
        g_pmn[blockIdx.x] = mn;
    }
}

#define FTH 1024
__global__ __launch_bounds__(FTH)
void cond_final_kernel(float* __restrict__ out) {
    __shared__ double sw[32][4];
    __shared__ float  swmx[32];
    __shared__ float  swmn[32];

    const int t = threadIdx.x;
    const int lane = t & 31;
    const int wid  = t >> 5;
    const unsigned FULL = 0xffffffffu;

    double a0 = 0.0, a1 = 0.0, a2 = 0.0, a3 = 0.0;
    float mx = 0.f, mn = 3.0e38f;
    for (int i = t; i < NBLOCKS; i += FTH) {
        a0 += g_pd[i][0]; a1 += g_pd[i][1]; a2 += g_pd[i][2]; a3 += g_pd[i][3];
        mx = fmaxf(mx, g_pmx[i]);
        mn = fminf(mn, g_pmn[i]);
    }
    #pragma unroll
    for (int off = 16; off > 0; off >>= 1) {
        a0 += __shfl_down_sync(FULL, a0, off);
        a1 += __shfl_down_sync(FULL, a1, off);
        a2 += __shfl_down_sync(FULL, a2, off);
        a3 += __shfl_down_sync(FULL, a3, off);
        mx = fmaxf(mx, __shfl_down_sync(FULL, mx, off));
        mn = fminf(mn, __shfl_down_sync(FULL, mn, off));
    }
    if (lane == 0) {
        sw[wid][0] = a0; sw[wid][1] = a1; sw[wid][2] = a2; sw[wid][3] = a3;
        swmx[wid] = mx; swmn[wid] = mn;
    }
    __syncthreads();

    if (wid == 0) {
        a0 = sw[lane][0]; a1 = sw[lane][1]; a2 = sw[lane][2]; a3 = sw[lane][3];
        mx = swmx[lane]; mn = swmn[lane];
        #pragma unroll
        for (int off = 16; off > 0; off >>= 1) {
            a0 += __shfl_down_sync(FULL, a0, off);
            a1 += __shfl_down_sync(FULL, a1, off);
            a2 += __shfl_down_sync(FULL, a2, off);
            a3 += __shfl_down_sync(FULL, a3, off);
            mx = fmaxf(mx, __shfl_down_sync(FULL, mx, off));
            mn = fminf(mn, __shfl_down_sync(FULL, mn, off));
        }
        if (lane == 0) {
            double maxe = (double)mx;   // max S^2
            double mine = (double)mn;   // min S^2
            const double NB = (double)BATCH * 25.0;
            double loss = (a2 / (double)BATCH) * 1e-5              // INV * mean fro
                        + (a0 / NB - 2.0 * (a1 / NB) + 1.0)        // DEV * mean (S-1)^2
                        + 0.5 * (log(maxe) - log(mine)) * 0.01     // COND
                        + 1e-6 * a3;                               // L1 * sum|outp|
            out[0] = (float)loss;
        }
    }
}

extern "C" void kernel_launch(void* const* d_in, const int* in_sizes, int n_in,
                              void* d_out, int out_size) {
    const float* inp  = (const float*)d_in[0];
    const float* outp = (const float*)d_in[1];
    float* out = (float*)d_out;
    (void)in_sizes; (void)n_in; (void)out_size;

    cond_main_kernel<<<NBLOCKS, THREADS>>>(inp, outp);
    cond_final_kernel<<<1, FTH>>>(out);
}

// round 16
// speedup vs baseline: 1.0353x; 1.0353x over previous
#include <cuda_runtime.h>
#include <cuda_fp16.h>
#include <math.h>

#define BATCH  32768
#define NWARPS 4
#define THREADS (NWARPS * 32)
#define NBLOCKS (BATCH / (NWARPS * 2))   // 4096: 2 matrices per warp
#define NSWEEP 3
#define H2STR 28                         // row stride in half2 units (112B, 16B-aligned)

__device__ double g_pd[NBLOCKS][4];   // sum_eig, sum_s, sum_fro, sum_absO
__device__ float  g_pmx[NBLOCKS];
__device__ float  g_pmn[NBLOCKS];

static __device__ __forceinline__ unsigned h2u(__half2 h) { return *reinterpret_cast<unsigned*>(&h); }
static __device__ __forceinline__ __half2  u2h(unsigned u) { return *reinterpret_cast<__half2*>(&u); }

__global__ __launch_bounds__(THREADS, 6)
void cond_main_kernel(const float* __restrict__ inp, const float* __restrict__ outp) {
    __shared__ __align__(16) __half2 Osh[NWARPS][25 * H2STR + 8];
    __shared__ double redd[NWARPS][4];
    __shared__ float  redmx[NWARPS];
    __shared__ float  redmn[NWARPS];

    const int w    = threadIdx.x >> 5;
    const int lane = threadIdx.x & 31;
    const int wg   = blockIdx.x * NWARPS + w;
    const int b0   = 2 * wg;               // this warp handles matrices b0, b0+1
    __half2* Os2 = Osh[w];

    const bool act25 = (lane < 25);
    const unsigned FULL = 0xffffffffu;

    const __half2 ONE2   = __float2half2_rn(1.0f);
    const __half2 ZERO2  = __float2half2_rn(0.0f);
    const __half2 EPSDEN = __float2half2_rn(1e-4f);
    const __half2 EIGHTH = __float2half2_rn(0.125f);
    const __half2 BMIN   = __float2half2_rn(0.3398f);   // alpha-max-beta-min hypot coeff

    float absO = 0.f;
    float froA = 0.f, froB = 0.f;
    float alA = 0.f, alB = 0.f;    // fp32 per-column ||col||^2 (trace source)
    __half2 v2[25];                // lo = matrix A column elem, hi = matrix B (x 1/8)

    // ---- prologue: load both O matrices packed, packed GEMM C = O@I ----
    {
        const float* OA = outp + (size_t)b0 * 625;
        const float* OB = OA + 625;
        const float* IA = inp + (size_t)b0 * 625;
        const float* IB = IA + 625;

        for (int idx = lane; idx < 625; idx += 32) {
            float a = OA[idx];
            float bv = OB[idx];
            absO += fabsf(a) + fabsf(bv);
            int i = idx / 25, j = idx - i * 25;
            Os2[i * H2STR + j] = __floats2half2_rn(a, bv);
        }
        __half2 Icol2[25];
        #pragma unroll
        for (int k = 0; k < 25; k++) {
            float a = act25 ? IA[k * 25 + lane] : 0.f;
            float bv = act25 ? IB[k * 25 + lane] : 0.f;
            Icol2[k] = __floats2half2_rn(a, bv);
        }
        __syncwarp();

        #pragma unroll
        for (int i = 0; i < 25; i++) {
            const uint4* row4 = reinterpret_cast<const uint4*>(Os2 + i * H2STR);
            __half2 acc = ZERO2;
            #pragma unroll
            for (int q = 0; q < 6; q++) {
                uint4 p = row4[q];
                acc = __hfma2(u2h(p.x), Icol2[4 * q + 0], acc);
                acc = __hfma2(u2h(p.y), Icol2[4 * q + 1], acc);
                acc = __hfma2(u2h(p.z), Icol2[4 * q + 2], acc);
                acc = __hfma2(u2h(p.w), Icol2[4 * q + 3], acc);
            }
            acc = __hfma2(Os2[i * H2STR + 24], Icol2[24], acc);
            float2 cf = __half22float2(acc);
            alA = fmaf(cf.x, cf.x, alA);
            alB = fmaf(cf.y, cf.y, alB);
            float eye = (i == lane) ? 1.f : 0.f;
            float dA = cf.x - eye, dB = cf.y - eye;
            if (act25) { froA = fmaf(dA, dA, froA); froB = fmaf(dB, dB, froB); }
            v2[i] = __hmul2(acc, EIGHTH);
        }
    }

    // alpha in scaled units (1/64), packed (A,B)
    __half2 a2 = __floats2half2_rn(alA * (1.f / 64.f), alB * (1.f / 64.f));
    __half2 f2  = ONE2;   // deferred column scale (product of cosines)
    __half2 rf2 = ONE2;   // 1/f, tracked incrementally

    int partner0 = (lane == 0) ? 0 : (25 - lane);
    if (lane >= 25) partner0 = 0;
    int partner = partner0;

    // One Jacobi round (tangent form, homogeneous-t, packed 2 matrices).
    auto round_body = [&]() {
        const bool active = act25 && (partner != lane);

        __half2 o2[25];
        __half2 d0 = ZERO2, d1 = ZERO2;
        #pragma unroll
        for (int i = 0; i < 12; i++) {
            o2[i] = u2h(__shfl_sync(FULL, h2u(v2[i]), partner));
            d0 = __hfma2(v2[i], o2[i], d0);
        }
        #pragma unroll
        for (int i = 12; i < 25; i++) {
            o2[i] = u2h(__shfl_sync(FULL, h2u(v2[i]), partner));
            d1 = __hfma2(v2[i], o2[i], d1);
        }
        __half2 vdot = __hadd2(d0, d1);
        __half2 a2o = u2h(__shfl_sync(FULL, h2u(a2), partner));
        __half2 f2o = u2h(__shfl_sync(FULL, h2u(f2), partner));

        __half2 g2  = __hmul2(__hmul2(f2, f2o), vdot);   // true <col,col_o>
        __half2 num = __hsub2(a2o, a2);
        __half2 tg  = __hadd2(g2, g2);                   // 2*gamma
        // t = 2g*sign(num) / (|num| + rad), rad ~ hypot(num, 2g) via amax+bmin
        __half2 ax = __habs2(num);
        __half2 ag = __habs2(tg);
        __half2 mx = __hmax2(ax, ag);
        __half2 mn = __hmin2(ax, ag);
        __half2 rad = __hfma2(mn, BMIN, mx);
        __half2 denom = __hmax2(__hadd2(ax, rad), EPSDEN);
        __half2 tnum = u2h(h2u(tg) ^ (h2u(num) & 0x80008000u));
        __half2 t2 = __hmul2(tnum, h2rcp(denom));
        if (!active) t2 = ZERO2;

        __half2 nt2 = __hneg2(t2);
        __half2 q2  = __hfma2(t2, t2, ONE2);   // 1 + t^2
        __half2 rq2 = h2rsqrt(q2);             // = c
        __half2 coef = __hmul2(nt2, __hmul2(f2o, rf2));
        #pragma unroll
        for (int i = 0; i < 25; i++)
            v2[i] = __hfma2(coef, o2[i], v2[i]);

        a2 = __hfma2(nt2, g2, a2);               // alpha' = alpha - t*gamma
        f2  = __hmul2(f2, rq2);                  // f *= c
        rf2 = __hmul2(rf2, __hmul2(q2, rq2));    // rf *= 1/c

        partner += 2;
        if (partner >= 25) partner -= 25;
    };

    // ---- packed one-sided Jacobi: 25 rounds/sweep = 6 groups of 4 + 1 ----
    for (int sweep = 0; sweep < NSWEEP; sweep++) {
        partner = partner0;
        #pragma unroll 1
        for (int g = 0; g < 6; g++) {
            round_body(); round_body(); round_body(); round_body();
            // renorm once per 4 rounds: f >= 0.0625 guaranteed between checks
            if (__low2float(f2) < 0.25f || __high2float(f2) < 0.25f) {
                #pragma unroll
                for (int i = 0; i < 25; i++) v2[i] = __hmul2(v2[i], f2);
                f2 = ONE2;
                rf2 = ONE2;
            }
        }
        round_body();
        // sweep end: fold scale; (half) alpha refresh kills drift
        #pragma unroll
        for (int i = 0; i < 25; i++) v2[i] = __hmul2(v2[i], f2);
        f2 = ONE2;
        rf2 = ONE2;
        if (sweep != NSWEEP - 1) {
            __half2 acc0 = ZERO2, acc1 = ZERO2;
            #pragma unroll
            for (int i = 0; i < 12; i++) acc0 = __hfma2(v2[i], v2[i], acc0);
            #pragma unroll
            for (int i = 12; i < 25; i++) acc1 = __hfma2(v2[i], v2[i], acc1);
            a2 = __hadd2(acc0, acc1);
        }
    }

    // ---- final norms in fp32 (scale back by 64) ----
    float aA = 0.f, aB = 0.f;
    #pragma unroll
    for (int i = 0; i < 25; i++) {
        float2 cf = __half22float2(v2[i]);
        aA = fmaf(cf.x, cf.x, aA);
        aB = fmaf(cf.y, cf.y, aB);
    }
    aA *= 64.f; aB *= 64.f;

    float acA = fmaxf(aA, 1e-12f), acB = fmaxf(aB, 1e-12f);
    // Sum S^2 from fp32 prologue alphas (trace invariance) — not from fp16 Jacobi.
    float suma = act25 ? (alA + alB) : 0.f;
    float sums = act25 ? (sqrtf(aA) + sqrtf(aB)) : 0.f;
    float mxa  = act25 ? fmaxf(acA, acB) : 0.f;
    float mna  = act25 ? fminf(acA, acB) : 3.0e38f;

    #pragma unroll
    for (int off = 16; off > 0; off >>= 1) {
        suma += __shfl_xor_sync(FULL, suma, off);
        sums += __shfl_xor_sync(FULL, sums, off);
        froA += __shfl_xor_sync(FULL, froA, off);
        froB += __shfl_xor_sync(FULL, froB, off);
        absO += __shfl_xor_sync(FULL, absO, off);
        mxa = fmaxf(mxa, __shfl_xor_sync(FULL, mxa, off));
        mna = fminf(mna, __shfl_xor_sync(FULL, mna, off));
    }
    if (lane == 0) {
        redd[w][0] = (double)suma;
        redd[w][1] = (double)sums;
        redd[w][2] = (double)(sqrtf(froA) + sqrtf(froB));
        redd[w][3] = (double)absO;
        redmx[w] = mxa;
        redmn[w] = mna;
    }
    __syncthreads();

    if (threadIdx.x == 0) {
        double s0 = 0.0, s1 = 0.0, s2 = 0.0, s3 = 0.0;
        float mx = 0.f, mn = 3.0e38f;
        #pragma unroll
        for (int i = 0; i < NWARPS; i++) {
            s0 += redd[i][0]; s1 += redd[i][1]; s2 += redd[i][2]; s3 += redd[i][3];
            mx = fmaxf(mx, redmx[i]);
            mn = fminf(mn, redmn[i]);
        }
        g_pd[blockIdx.x][0] = s0;
        g_pd[blockIdx.x][1] = s1;
        g_pd[blockIdx.x][2] = s2;
        g_pd[blockIdx.x][3] = s3;
        g_pmx[blockIdx.x] = mx;
        g_pmn[blockIdx.x] = mn;
    }
}

#define FTH 1024
__global__ __launch_bounds__(FTH)
void cond_final_kernel(float* __restrict__ out) {
    __shared__ double sd[FTH][4];
    __shared__ float  smx[FTH];
    __shared__ float  smn[FTH];

    const int t = threadIdx.x;
    double a0 = 0.0, a1 = 0.0, a2 = 0.0, a3 = 0.0;
    float mx = 0.f, mn = 3.0e38f;
    for (int i = t; i < NBLOCKS; i += FTH) {
        a0 += g_pd[i][0]; a1 += g_pd[i][1]; a2 += g_pd[i][2]; a3 += g_pd[i][3];
        mx = fmaxf(mx, g_pmx[i]);
        mn = fminf(mn, g_pmn[i]);
    }
    sd[t][0] = a0; sd[t][1] = a1; sd[t][2] = a2; sd[t][3] = a3;
    smx[t] = mx; smn[t] = mn;
    __syncthreads();

    for (int off = FTH / 2; off > 0; off >>= 1) {
        if (t < off) {
            sd[t][0] += sd[t + off][0];
            sd[t][1] += sd[t + off][1];
            sd[t][2] += sd[t + off][2];
            sd[t][3] += sd[t + off][3];
            smx[t] = fmaxf(smx[t], smx[t + off]);
            smn[t] = fminf(smn[t], smn[t + off]);
        }
        __syncthreads();
    }

    if (t == 0) {
        double maxe = (double)smx[0];   // max S^2
        double mine = (double)smn[0];   // min S^2
        const double NB = (double)BATCH * 25.0;
        double loss = (sd[0][2] / (double)BATCH) * 1e-5              // INV * mean fro
                    + (sd[0][0] / NB - 2.0 * (sd[0][1] / NB) + 1.0)  // DEV * mean (S-1)^2
                    + 0.5 * (log(maxe) - log(mine)) * 0.01           // COND
                    + 1e-6 * sd[0][3];                               // L1 * sum|outp|
        out[0] = (float)loss;
    }
}

extern "C" void kernel_launch(void* const* d_in, const int* in_sizes, int n_in,
                              void* d_out, int out_size) {
    const float* inp  = (const float*)d_in[0];
    const float* outp = (const float*)d_in[1];
    float* out = (float*)d_out;
    (void)in_sizes; (void)n_in; (void)out_size;

    cond_main_kernel<<<NBLOCKS, THREADS>>>(inp, outp);
    cond_final_kernel<<<1, FTH>>>(out);
}

// round 17
// speedup vs baseline: 1.0775x; 1.0408x over previous
#include <cuda_runtime.h>
#include <cuda_fp16.h>
#include <math.h>

#define BATCH  32768
#define NWARPS 4
#define THREADS (NWARPS * 32)
#define NBLOCKS (BATCH / (NWARPS * 2))   // 4096: 2 matrices per warp
#define NSWEEP 3
#define H2STR 28                         // row stride in half2 units (112B, 16B-aligned)

__device__ double g_sum_eig;
__device__ double g_sum_s;
__device__ double g_sum_fro;
__device__ double g_sum_absO;
__device__ unsigned int g_max_bits;
__device__ unsigned int g_min_bits;

static __device__ __forceinline__ unsigned h2u(__half2 h) { return *reinterpret_cast<unsigned*>(&h); }
static __device__ __forceinline__ __half2  u2h(unsigned u) { return *reinterpret_cast<__half2*>(&u); }

__global__ void cond_init_kernel() {
    g_sum_eig = 0.0;
    g_sum_s = 0.0;
    g_sum_fro = 0.0;
    g_sum_absO = 0.0;
    g_max_bits = 0u;
    g_min_bits = 0x7f7fffffu;   // +FLT_MAX
}

__global__ __launch_bounds__(THREADS, 6)
void cond_main_kernel(const float* __restrict__ inp, const float* __restrict__ outp) {
    __shared__ __align__(16) __half2 Osh[NWARPS][25 * H2STR + 8];
    __shared__ double redd[NWARPS][4];
    __shared__ float  redmx[NWARPS];
    __shared__ float  redmn[NWARPS];

    const int w    = threadIdx.x >> 5;
    const int lane = threadIdx.x & 31;
    const int wg   = blockIdx.x * NWARPS + w;
    const int b0   = 2 * wg;               // this warp handles matrices b0, b0+1
    __half2* Os2 = Osh[w];

    const bool act25 = (lane < 25);
    const unsigned FULL = 0xffffffffu;

    const __half2 ONE2   = __float2half2_rn(1.0f);
    const __half2 ZERO2  = __float2half2_rn(0.0f);
    const __half2 EPSDEN = __float2half2_rn(1e-4f);
    const __half2 EIGHTH = __float2half2_rn(0.125f);
    const __half2 BMIN   = __float2half2_rn(0.3398f);   // alpha-max-beta-min hypot coeff

    float absO = 0.f;
    float froA = 0.f, froB = 0.f;
    float alA = 0.f, alB = 0.f;    // fp32 per-column ||col||^2 (trace source)
    __half2 v2[25];                // lo = matrix A column elem, hi = matrix B (x 1/8)

    // ---- prologue: load both O matrices packed, packed GEMM C = O@I ----
    {
        const float* OA = outp + (size_t)b0 * 625;
        const float* OB = OA + 625;
        const float* IA = inp + (size_t)b0 * 625;
        const float* IB = IA + 625;

        for (int idx = lane; idx < 625; idx += 32) {
            float a = OA[idx];
            float bv = OB[idx];
            absO += fabsf(a) + fabsf(bv);
            int i = idx / 25, j = idx - i * 25;
            Os2[i * H2STR + j] = __floats2half2_rn(a, bv);
        }
        __half2 Icol2[25];
        #pragma unroll
        for (int k = 0; k < 25; k++) {
            float a = act25 ? IA[k * 25 + lane] : 0.f;
            float bv = act25 ? IB[k * 25 + lane] : 0.f;
            Icol2[k] = __floats2half2_rn(a, bv);
        }
        __syncwarp();

        #pragma unroll
        for (int i = 0; i < 25; i++) {
            const uint4* row4 = reinterpret_cast<const uint4*>(Os2 + i * H2STR);
            __half2 acc = ZERO2;
            #pragma unroll
            for (int q = 0; q < 6; q++) {
                uint4 p = row4[q];
                acc = __hfma2(u2h(p.x), Icol2[4 * q + 0], acc);
                acc = __hfma2(u2h(p.y), Icol2[4 * q + 1], acc);
                acc = __hfma2(u2h(p.z), Icol2[4 * q + 2], acc);
                acc = __hfma2(u2h(p.w), Icol2[4 * q + 3], acc);
            }
            acc = __hfma2(Os2[i * H2STR + 24], Icol2[24], acc);
            float2 cf = __half22float2(acc);
            alA = fmaf(cf.x, cf.x, alA);
            alB = fmaf(cf.y, cf.y, alB);
            float eye = (i == lane) ? 1.f : 0.f;
            float dA = cf.x - eye, dB = cf.y - eye;
            if (act25) { froA = fmaf(dA, dA, froA); froB = fmaf(dB, dB, froB); }
            v2[i] = __hmul2(acc, EIGHTH);
        }
    }

    // alpha in scaled units (1/64), packed (A,B)
    __half2 a2 = __floats2half2_rn(alA * (1.f / 64.f), alB * (1.f / 64.f));
    __half2 f2  = ONE2;   // deferred column scale (product of cosines)
    __half2 rf2 = ONE2;   // 1/f, tracked incrementally

    int partner0 = (lane == 0) ? 0 : (25 - lane);
    if (lane >= 25) partner0 = 0;
    int partner = partner0;

    // One Jacobi round (tangent form, homogeneous-t, packed 2 matrices).
    auto round_body = [&]() {
        const bool active = act25 && (partner != lane);

        __half2 o2[25];
        __half2 d0 = ZERO2, d1 = ZERO2;
        #pragma unroll
        for (int i = 0; i < 12; i++) {
            o2[i] = u2h(__shfl_sync(FULL, h2u(v2[i]), partner));
            d0 = __hfma2(v2[i], o2[i], d0);
        }
        #pragma unroll
        for (int i = 12; i < 25; i++) {
            o2[i] = u2h(__shfl_sync(FULL, h2u(v2[i]), partner));
            d1 = __hfma2(v2[i], o2[i], d1);
        }
        __half2 vdot = __hadd2(d0, d1);
        __half2 a2o = u2h(__shfl_sync(FULL, h2u(a2), partner));
        __half2 f2o = u2h(__shfl_sync(FULL, h2u(f2), partner));

        __half2 g2  = __hmul2(__hmul2(f2, f2o), vdot);   // true <col,col_o>
        __half2 num = __hsub2(a2o, a2);
        __half2 tg  = __hadd2(g2, g2);                   // 2*gamma
        // t = 2g*sign(num) / (|num| + rad), rad ~ hypot(num, 2g) via amax+bmin
        __half2 ax = __habs2(num);
        __half2 ag = __habs2(tg);
        __half2 mx = __hmax2(ax, ag);
        __half2 mn = __hmin2(ax, ag);
        __half2 rad = __hfma2(mn, BMIN, mx);
        __half2 denom = __hmax2(__hadd2(ax, rad), EPSDEN);
        __half2 tnum = u2h(h2u(tg) ^ (h2u(num) & 0x80008000u));
        __half2 t2 = __hmul2(tnum, h2rcp(denom));
        if (!active) t2 = ZERO2;

        __half2 nt2 = __hneg2(t2);
        __half2 q2  = __hfma2(t2, t2, ONE2);   // 1 + t^2
        __half2 rq2 = h2rsqrt(q2);             // = c
        __half2 coef = __hmul2(nt2, __hmul2(f2o, rf2));
        #pragma unroll
        for (int i = 0; i < 25; i++)
            v2[i] = __hfma2(coef, o2[i], v2[i]);

        a2 = __hfma2(nt2, g2, a2);               // alpha' = alpha - t*gamma
        f2  = __hmul2(f2, rq2);                  // f *= c
        rf2 = __hmul2(rf2, __hmul2(q2, rq2));    // rf *= 1/c

        partner += 2;
        if (partner >= 25) partner -= 25;
    };

    // ---- packed one-sided Jacobi: 25 rounds/sweep = 6 groups of 4 + 1 ----
    for (int sweep = 0; sweep < NSWEEP; sweep++) {
        partner = partner0;
        #pragma unroll 1
        for (int g = 0; g < 6; g++) {
            round_body(); round_body(); round_body(); round_body();
            // renorm once per 4 rounds: f >= 0.0625 guaranteed between checks
            if (__low2float(f2) < 0.25f || __high2float(f2) < 0.25f) {
                #pragma unroll
                for (int i = 0; i < 25; i++) v2[i] = __hmul2(v2[i], f2);
                f2 = ONE2;
                rf2 = ONE2;
            }
        }
        round_body();
        // sweep end: fold scale; (half) alpha refresh kills drift
        #pragma unroll
        for (int i = 0; i < 25; i++) v2[i] = __hmul2(v2[i], f2);
        f2 = ONE2;
        rf2 = ONE2;
        if (sweep != NSWEEP - 1) {
            __half2 acc0 = ZERO2, acc1 = ZERO2;
            #pragma unroll
            for (int i = 0; i < 12; i++) acc0 = __hfma2(v2[i], v2[i], acc0);
            #pragma unroll
            for (int i = 12; i < 25; i++) acc1 = __hfma2(v2[i], v2[i], acc1);
            a2 = __hadd2(acc0, acc1);
        }
    }

    // ---- final norms in fp32 (scale back by 64) ----
    float aA = 0.f, aB = 0.f;
    #pragma unroll
    for (int i = 0; i < 25; i++) {
        float2 cf = __half22float2(v2[i]);
        aA = fmaf(cf.x, cf.x, aA);
        aB = fmaf(cf.y, cf.y, aB);
    }
    aA *= 64.f; aB *= 64.f;

    float acA = fmaxf(aA, 1e-12f), acB = fmaxf(aB, 1e-12f);
    // Sum S^2 from fp32 prologue alphas (trace invariance) — not from fp16 Jacobi.
    float suma = act25 ? (alA + alB) : 0.f;
    float sums = act25 ? (sqrtf(aA) + sqrtf(aB)) : 0.f;
    float mxa  = act25 ? fmaxf(acA, acB) : 0.f;
    float mna  = act25 ? fminf(acA, acB) : 3.0e38f;

    #pragma unroll
    for (int off = 16; off > 0; off >>= 1) {
        suma += __shfl_xor_sync(FULL, suma, off);
        sums += __shfl_xor_sync(FULL, sums, off);
        froA += __shfl_xor_sync(FULL, froA, off);
        froB += __shfl_xor_sync(FULL, froB, off);
        absO += __shfl_xor_sync(FULL, absO, off);
        mxa = fmaxf(mxa, __shfl_xor_sync(FULL, mxa, off));
        mna = fminf(mna, __shfl_xor_sync(FULL, mna, off));
    }
    if (lane == 0) {
        redd[w][0] = (double)suma;
        redd[w][1] = (double)sums;
        redd[w][2] = (double)(sqrtf(froA) + sqrtf(froB));
        redd[w][3] = (double)absO;
        redmx[w] = mxa;
        redmn[w] = mna;
    }
    __syncthreads();

    // One atomic set per block — issued at staggered block-exit times, fully
    // absorbed into the compute shadow of still-running blocks.
    if (threadIdx.x == 0) {
        double s0 = 0.0, s1 = 0.0, s2 = 0.0, s3 = 0.0;
        float mx = 0.f, mn = 3.0e38f;
        #pragma unroll
        for (int i = 0; i < NWARPS; i++) {
            s0 += redd[i][0]; s1 += redd[i][1]; s2 += redd[i][2]; s3 += redd[i][3];
            mx = fmaxf(mx, redmx[i]);
            mn = fminf(mn, redmn[i]);
        }
        atomicAdd(&g_sum_eig, s0);
        atomicAdd(&g_sum_s, s1);
        atomicAdd(&g_sum_fro, s2);
        atomicAdd(&g_sum_absO, s3);
        atomicMax(&g_max_bits, __float_as_uint(mx));
        atomicMin(&g_min_bits, __float_as_uint(mn));
    }
}

__global__ void cond_final_kernel(float* __restrict__ out) {
    double maxe = (double)__uint_as_float(g_max_bits);   // max S^2
    double mine = (double)__uint_as_float(g_min_bits);   // min S^2
    const double NB = (double)BATCH * 25.0;
    double loss = (g_sum_fro / (double)BATCH) * 1e-5               // INV * mean fro
                + (g_sum_eig / NB - 2.0 * (g_sum_s / NB) + 1.0)    // DEV * mean (S-1)^2
                + 0.5 * (log(maxe) - log(mine)) * 0.01             // COND
                + 1e-6 * g_sum_absO;                                // L1 * sum|outp|
    out[0] = (float)loss;
}

extern "C" void kernel_launch(void* const* d_in, const int* in_sizes, int n_in,
                              void* d_out, int out_size) {
    const float* inp  = (const float*)d_in[0];
    const float* outp = (const float*)d_in[1];
    float* out = (float*)d_out;
    (void)in_sizes; (void)n_in; (void)out_size;

    cond_init_kernel<<<1, 1>>>();
    cond_main_kernel<<<NBLOCKS, THREADS>>>(inp, outp);
    cond_final_kernel<<<1, 1>>>(out);
}